// round 11
// baseline (speedup 1.0000x reference)
#include <cuda_runtime.h>
#include <cuda_fp16.h>
#include <cstdint>

// CachedMPS on GB300 — fp16 m16n8k16 2-way-split HMMA chain, paired steps,
// R11: split-k warp pairs. Two warps per 16-row group each do half the k-dim
// (48 MMAs instead of 96), doubling chip warp count (2048->4096, 6.9/SMSP) so
// tensor / LDS / ALU phases overlap across warps. Per pair: fold partial,
// exchange 16 f32 via smem + 64-thread named barrier, sum -> replicated acc.

#define DEV_INLINE __device__ __forceinline__

static constexpr int D     = 32;
static constexpr int L     = 256;
static constexpr int NPAIR = 127;
static constexpr int C     = 10;
static constexpr int TPB   = 256;             // 8 warps = 4 groups x 2 halves
static constexpr int ROWS_PER_CTA = 64;       // 4 groups x 16 rows
static constexpr float HALF_PI = 1.57079632679489662f;
static constexpr float LO_SCALE = 1024.0f;
static constexpr float LO_INV   = 1.0f / 1024.0f;

// composite-W scratch: [NPAIR][4096] u32 (f16x2-packed hi/lo, frag-native)
__device__ unsigned g_Bt[(size_t)NPAIR * 4096];

DEV_INLINE unsigned smem_u32(const void* p) {
    unsigned r;
    asm("{ .reg .u64 t; cvta.to.shared.u64 t, %1; cvt.u32.u64 %0, t; }" : "=r"(r) : "l"(p));
    return r;
}
DEV_INLINE void cp16(unsigned dst, const void* src) {
    asm volatile("cp.async.cg.shared.global [%0], [%1], 16;" :: "r"(dst), "l"(src));
}
DEV_INLINE void cp_commit() { asm volatile("cp.async.commit_group;"); }
DEV_INLINE void cp_wait0()  { asm volatile("cp.async.wait_group 0;" ::: "memory"); }

DEV_INLINE unsigned packh2(float lo, float hi) {
    unsigned r; asm("cvt.rn.f16x2.f32 %0, %1, %2;" : "=r"(r) : "f"(hi), "f"(lo));
    return r;
}
DEV_INLINE void unpackh2(unsigned u, float& lo, float& hi) {
    const __half2 h = *reinterpret_cast<const __half2*>(&u);
    lo = __low2float(h); hi = __high2float(h);
}

DEV_INLINE void mma16(float* c, const unsigned* a, unsigned b0, unsigned b1) {
    asm("mma.sync.aligned.m16n8k16.row.col.f32.f16.f16.f32 "
        "{%0,%1,%2,%3}, {%4,%5,%6,%7}, {%8,%9}, {%0,%1,%2,%3};"
        : "+f"(c[0]), "+f"(c[1]), "+f"(c[2]), "+f"(c[3])
        : "r"(a[0]), "r"(a[1]), "r"(a[2]), "r"(a[3]), "r"(b0), "r"(b1));
}

// ---- prep: composite pair products -> f16 hi/lo, B-frag-native (R10-verified) ----
__global__ void prep_pairs(const float* __restrict__ cores_mid) {
    __shared__ float sW0[2048], sW1[2048];
    const int p = blockIdx.x;
    const float* s0 = cores_mid + (size_t)(2 * p) * 2048;
    const float* s1 = cores_mid + (size_t)(2 * p + 1) * 2048;
    for (int i = threadIdx.x; i < 2048; i += blockDim.x) { sW0[i] = s0[i]; sW1[i] = s1[i]; }
    __syncthreads();

    unsigned* dst = g_Bt + (size_t)p * 4096;
    for (int i = threadIdx.x; i < 4096; i += blockDim.x) {
        const int s = i & 3, lane = (i >> 2) & 31, tj = i >> 7;
        const int T = tj >> 2, j = tj & 3;
        const int q = lane & 3, g = lane >> 2;
        const int reg = s & 1, term = s >> 1;
        const int k0 = 16 * T + 2 * q + 8 * reg;
        const int n  = 8 * j + g;

        float v[2];
        #pragma unroll
        for (int e = 0; e < 2; e++) {
            const int k = k0 + e, ci = k >> 5, a = k & 31;
            const float* r0 = sW0 + (ci & 1) * 1024 + a * 32;
            const float* r1 = sW1 + (ci >> 1) * 1024 + n;
            float acc = 0.f;
            #pragma unroll 8
            for (int cc = 0; cc < 32; cc++) acc += r0[cc] * r1[cc * 32];
            v[e] = acc;
        }
        const unsigned hi = packh2(v[0], v[1]);
        if (term == 0) {
            dst[i] = hi;
        } else {
            float h0, h1; unpackh2(hi, h0, h1);
            dst[i] = packh2(LO_SCALE * (v[0] - h0), LO_SCALE * (v[1] - h1));
        }
    }
}

__global__ void __launch_bounds__(TPB, 4)
mps_hmma_kernel(const float* __restrict__ x,
                const float* __restrict__ core0,
                const float* __restrict__ coreN,
                float* __restrict__ out, int B)
{
    __shared__ __align__(16) unsigned sW[2][4096];   // 32KB: 2 stages of W
    __shared__ __align__(16) float sEx[4][2][512];   // 16KB: [group][half][(j*32+lane)*4+e]

    const int tid  = threadIdx.x;
    const int lane = tid & 31;
    const int w    = tid >> 5;
    const int pw   = w >> 1;       // row group 0..3
    const int h    = w & 1;        // k-half 0/1
    const int q    = lane & 3;
    const int g    = lane >> 2;
    const int rowbase = blockIdx.x * ROWS_PER_CTA + pw * 16;

    int rows[2];
    rows[0] = min(rowbase + g,     B - 1);
    rows[1] = min(rowbase + g + 8, B - 1);

    // prefetch pair-0 tile (16KB, 4 cp16/thread)
    {
        const unsigned* gsrc = g_Bt;
        const unsigned sb = smem_u32(&sW[0][0]);
        #pragma unroll
        for (int i = 0; i < 4; i++) {
            const int idx = tid + i * TPB;
            cp16(sb + idx * 16, gsrc + idx * 4);
        }
        cp_commit();
    }

    // ---- init acc = M0, c-frag layout (replicated in both halves) ----
    float acc[16];
    #pragma unroll
    for (int rs = 0; rs < 2; rs++) {
        float s0, c0;
        __sincosf(HALF_PI * __ldg(x + (size_t)rows[rs] * L), &s0, &c0);
        #pragma unroll
        for (int j = 0; j < 4; j++)
            #pragma unroll
            for (int pp = 0; pp < 2; pp++) {
                const int col = 8 * j + 2 * q + pp;
                acc[4 * j + 2 * rs + pp] = c0 * core0[col] + s0 * core0[32 + col];
            }
    }

    // pair-0 scalars
    float sc[4][2];
    #pragma unroll
    for (int rs = 0; rs < 2; rs++) {
        float s1v, c1v, s2v, c2v;
        __sincosf(HALF_PI * __ldg(x + (size_t)rows[rs] * L + 1), &s1v, &c1v);
        __sincosf(HALF_PI * __ldg(x + (size_t)rows[rs] * L + 2), &s2v, &c2v);
        sc[0][rs] = c1v * c2v;  sc[1][rs] = s1v * c2v;
        sc[2][rs] = c1v * s2v;  sc[3][rs] = s1v * s2v;
    }

    float* exMine  = &sEx[pw][h][0];
    const float* exOther = &sEx[pw][1 - h][0];

    // ---- 127 composite steps ----
    for (int p = 0; p < NPAIR; p++) {
        cp_wait0();
        __syncthreads();   // W stage ready; prev exchange reads complete

        if (p + 1 < NPAIR) {
            const unsigned* gsrc = g_Bt + (size_t)(p + 1) * 4096;
            const unsigned sb = smem_u32(&sW[(p + 1) & 1][0]);
            #pragma unroll
            for (int i = 0; i < 4; i++) {
                const int idx = tid + i * TPB;
                cp16(sb + idx * 16, gsrc + idx * 4);
            }
            cp_commit();
        }

        const unsigned* W = &sW[p & 1][0];

        float nacc[16], clo[16];
        #pragma unroll
        for (int k = 0; k < 16; k++) { nacc[k] = 0.f; clo[k] = 0.f; }

        // this warp's k-half: T = 4h + tt, tt = 0..3
        #pragma unroll
        for (int tt = 0; tt < 4; tt++) {
            const int T  = 4 * h + tt;
            const int ci = 2 * h + (tt >> 1);
            const int j1 = 2 * (tt & 1), j2 = j1 + 1;
            const float sc0 = sc[ci][0], sc1 = sc[ci][1];

            const float v00 = sc0 * acc[4 * j1 + 0], v01 = sc0 * acc[4 * j1 + 1];
            const float v10 = sc1 * acc[4 * j1 + 2], v11 = sc1 * acc[4 * j1 + 3];
            const float v20 = sc0 * acc[4 * j2 + 0], v21 = sc0 * acc[4 * j2 + 1];
            const float v30 = sc1 * acc[4 * j2 + 2], v31 = sc1 * acc[4 * j2 + 3];

            unsigned ahi[4], alo[4];
            ahi[0] = packh2(v00, v01); ahi[1] = packh2(v10, v11);
            ahi[2] = packh2(v20, v21); ahi[3] = packh2(v30, v31);
            {
                float h0, h1;
                unpackh2(ahi[0], h0, h1);
                alo[0] = packh2(LO_SCALE * (v00 - h0), LO_SCALE * (v01 - h1));
                unpackh2(ahi[1], h0, h1);
                alo[1] = packh2(LO_SCALE * (v10 - h0), LO_SCALE * (v11 - h1));
                unpackh2(ahi[2], h0, h1);
                alo[2] = packh2(LO_SCALE * (v20 - h0), LO_SCALE * (v21 - h1));
                unpackh2(ahi[3], h0, h1);
                alo[3] = packh2(LO_SCALE * (v30 - h0), LO_SCALE * (v31 - h1));
            }

            #pragma unroll
            for (int j = 0; j < 4; j++) {
                const uint4 b = *reinterpret_cast<const uint4*>(
                    W + ((size_t)(T * 4 + j) * 32 + lane) * 4);
                mma16(&nacc[4 * j], ahi, b.x, b.y);   // hi*Bhi
                mma16(&clo[4 * j],  ahi, b.z, b.w);   // hi*Blo'
                mma16(&clo[4 * j],  alo, b.x, b.y);   // lo'*Bhi
            }
        }

        // next pair's scalars (x-only; overlaps in-flight MMAs)
        if (p + 1 < NPAIR) {
            #pragma unroll
            for (int rs = 0; rs < 2; rs++) {
                float s1v, c1v, s2v, c2v;
                __sincosf(HALF_PI * __ldg(x + (size_t)rows[rs] * L + (2 * p + 3)), &s1v, &c1v);
                __sincosf(HALF_PI * __ldg(x + (size_t)rows[rs] * L + (2 * p + 4)), &s2v, &c2v);
                sc[0][rs] = c1v * c2v;  sc[1][rs] = s1v * c2v;
                sc[2][rs] = c1v * s2v;  sc[3][rs] = s1v * s2v;
            }
        }

        // fold partial and exchange with the other k-half
        float part[16];
        #pragma unroll
        for (int k = 0; k < 16; k++) part[k] = fmaf(clo[k], LO_INV, nacc[k]);

        #pragma unroll
        for (int j = 0; j < 4; j++)
            *reinterpret_cast<float4*>(exMine + (j * 32 + lane) * 4) =
                make_float4(part[4 * j], part[4 * j + 1], part[4 * j + 2], part[4 * j + 3]);

        asm volatile("bar.sync %0, 64;" :: "r"(pw + 1) : "memory");

        #pragma unroll
        for (int j = 0; j < 4; j++) {
            const float4 o = *reinterpret_cast<const float4*>(exOther + (j * 32 + lane) * 4);
            acc[4 * j]     = part[4 * j]     + o.x;
            acc[4 * j + 1] = part[4 * j + 1] + o.y;
            acc[4 * j + 2] = part[4 * j + 2] + o.z;
            acc[4 * j + 3] = part[4 * j + 3] + o.w;
        }

        // range control every 4 pairs (identical in both halves -> stays replicated)
        if ((p & 3) == 3) {
            #pragma unroll
            for (int rs = 0; rs < 2; rs++) {
                float ss = 0.f;
                #pragma unroll
                for (int j = 0; j < 4; j++) {
                    const float v0 = acc[4 * j + 2 * rs];
                    const float v1 = acc[4 * j + 2 * rs + 1];
                    ss += v0 * v0 + v1 * v1;
                }
                ss += __shfl_xor_sync(0xffffffffu, ss, 1);
                ss += __shfl_xor_sync(0xffffffffu, ss, 2);
                const float r = rsqrtf(ss);
                #pragma unroll
                for (int j = 0; j < 4; j++) {
                    acc[4 * j + 2 * rs]     *= r;
                    acc[4 * j + 2 * rs + 1] *= r;
                }
            }
        }
    }

    // ---- readout (h==0 warps only; acc replicated): eps-free normalize ----
    if (h == 0) {
        #pragma unroll
        for (int rs = 0; rs < 2; rs++) {
            const int row = rowbase + g + 8 * rs;

            float ss = 0.f;
            #pragma unroll
            for (int j = 0; j < 4; j++) {
                const float v0 = acc[4 * j + 2 * rs];
                const float v1 = acc[4 * j + 2 * rs + 1];
                ss += v0 * v0 + v1 * v1;
            }
            ss += __shfl_xor_sync(0xffffffffu, ss, 1);
            ss += __shfl_xor_sync(0xffffffffu, ss, 2);
            const float inv = rsqrtf(ss);           // NO eps (R1 lesson)

            float sL, cL;
            __sincosf(HALF_PI * __ldg(x + (size_t)rows[rs] * L + (L - 1)), &sL, &cL);

            float lg[C];
            #pragma unroll
            for (int cc = 0; cc < C; cc++) lg[cc] = 0.f;
            #pragma unroll
            for (int j = 0; j < 4; j++)
                #pragma unroll
                for (int pp = 0; pp < 2; pp++) {
                    const int col = 8 * j + 2 * q + pp;
                    const float m = acc[4 * j + 2 * rs + pp];
                    #pragma unroll
                    for (int cc = 0; cc < C; cc++) {
                        const float wv = cL * coreN[col * C + cc]
                                       + sL * coreN[D * C + col * C + cc];
                        lg[cc] += m * wv;
                    }
                }
            #pragma unroll
            for (int cc = 0; cc < C; cc++) {
                lg[cc] += __shfl_xor_sync(0xffffffffu, lg[cc], 1);
                lg[cc] += __shfl_xor_sync(0xffffffffu, lg[cc], 2);
            }
            if (q == 0 && row < B) {
                #pragma unroll
                for (int cc = 0; cc < C; cc++)
                    out[(size_t)row * C + cc] = lg[cc] * inv;
            }
        }
    }
}

extern "C" void kernel_launch(void* const* d_in, const int* in_sizes, int n_in,
                              void* d_out, int out_size)
{
    const float* x         = (const float*)d_in[0];
    const float* core0     = (const float*)d_in[1];
    const float* cores_mid = (const float*)d_in[2];
    const float* coreN     = (const float*)d_in[3];
    float* out = (float*)d_out;

    const int B = in_sizes[0] / L;
    const int grid = (B + ROWS_PER_CTA - 1) / ROWS_PER_CTA;   // 512 for B=32768

    prep_pairs<<<NPAIR, 256>>>(cores_mid);
    mps_hmma_kernel<<<grid, TPB>>>(x, core0, coreN, out, B);
}

// round 12
// speedup vs baseline: 1.6487x; 1.6487x over previous
#include <cuda_runtime.h>
#include <cuda_fp16.h>
#include <cstdint>

// CachedMPS on GB300 — fp16 m16n8k16 split HMMA chain, paired steps.
// R12 (= R10 minus the correction accumulator): scale-engineered so all three
// split terms accumulate into one f32 accumulator family.
//   - W stored x64 in prep -> B-lo is normal-range f16 (no subnormal bets)
//   - chain normalized to 256 every 2 pairs -> A-hi/lo in f16 sweet spot
//   - homogeneous chain absorbs all scales; final eps-free unit-normalize
// Split is exact mask-truncation: hi = v & 0xFFFFE000 (f16-exact for normal
// range), lo = v - hi; dropped alo*blo ~ 2^-22.

#define DEV_INLINE __device__ __forceinline__

static constexpr int D     = 32;
static constexpr int L     = 256;
static constexpr int NPAIR = 127;
static constexpr int C     = 10;
static constexpr int TPB   = 128;             // 4 warps x 16 rows = 64 rows/CTA
static constexpr int ROWS_PER_CTA = 64;
static constexpr float HALF_PI = 1.57079632679489662f;
static constexpr float W_SCALE  = 64.0f;      // prep-side W scaling
static constexpr float NORM_TGT = 256.0f;     // chain rescale target
static constexpr unsigned H_MASK = 0xFFFFE000u;  // f32 -> top-10-mantissa (f16-exact)

// composite-W scratch: [NPAIR][4096] u32 (f16x2-packed hi/lo, frag-native)
__device__ unsigned g_Bt[(size_t)NPAIR * 4096];

DEV_INLINE unsigned smem_u32(const void* p) {
    unsigned r;
    asm("{ .reg .u64 t; cvta.to.shared.u64 t, %1; cvt.u32.u64 %0, t; }" : "=r"(r) : "l"(p));
    return r;
}
DEV_INLINE void cp16(unsigned dst, const void* src) {
    asm volatile("cp.async.cg.shared.global [%0], [%1], 16;" :: "r"(dst), "l"(src));
}
DEV_INLINE void cp_commit() { asm volatile("cp.async.commit_group;"); }
DEV_INLINE void cp_wait0()  { asm volatile("cp.async.wait_group 0;" ::: "memory"); }

DEV_INLINE unsigned packh2(float lo, float hi) {
    unsigned r; asm("cvt.rn.f16x2.f32 %0, %1, %2;" : "=r"(r) : "f"(hi), "f"(lo));
    return r;
}
DEV_INLINE void unpackh2(unsigned u, float& lo, float& hi) {
    const __half2 h = *reinterpret_cast<const __half2*>(&u);
    lo = __low2float(h); hi = __high2float(h);
}

DEV_INLINE void mma16(float* c, const unsigned* a, unsigned b0, unsigned b1) {
    asm("mma.sync.aligned.m16n8k16.row.col.f32.f16.f16.f32 "
        "{%0,%1,%2,%3}, {%4,%5,%6,%7}, {%8,%9}, {%0,%1,%2,%3};"
        : "+f"(c[0]), "+f"(c[1]), "+f"(c[2]), "+f"(c[3])
        : "r"(a[0]), "r"(a[1]), "r"(a[2]), "r"(a[3]), "r"(b0), "r"(b1));
}

// exact mask split (valid for |v| in f16 normal range; tail negligible)
DEV_INLINE void msplit(float v, float& hf, float& lf) {
    const unsigned h = __float_as_uint(v) & H_MASK;
    hf = __uint_as_float(h);
    lf = v - hf;
}

// ---- prep: composite pair products x64 -> f16 hi/lo, B-frag-native ----
// u32 slot i: s=i&3 (0=hi r0,1=hi r1,2=lo r0,3=lo r1), lane=(i>>2)&31,
// tj=i>>7: T=tj>>2, j=tj&3; q=lane&3, g=lane>>2; reg r: k0=16T+2q+8r;
// pack {W[k0][n], W[k0+1][n]}, n=8j+g; W[k][n] with k=ci*32+a =
// 64 * sum_cc W0[ci&1][a][cc]*W1[ci>>1][cc][n].
__global__ void prep_pairs(const float* __restrict__ cores_mid) {
    __shared__ float sW0[2048], sW1[2048];
    const int p = blockIdx.x;
    const float* s0 = cores_mid + (size_t)(2 * p) * 2048;
    const float* s1 = cores_mid + (size_t)(2 * p + 1) * 2048;
    for (int i = threadIdx.x; i < 2048; i += blockDim.x) { sW0[i] = s0[i]; sW1[i] = s1[i]; }
    __syncthreads();

    unsigned* dst = g_Bt + (size_t)p * 4096;
    for (int i = threadIdx.x; i < 4096; i += blockDim.x) {
        const int s = i & 3, lane = (i >> 2) & 31, tj = i >> 7;
        const int T = tj >> 2, j = tj & 3;
        const int q = lane & 3, g = lane >> 2;
        const int reg = s & 1, term = s >> 1;
        const int k0 = 16 * T + 2 * q + 8 * reg;
        const int n  = 8 * j + g;

        float v[2];
        #pragma unroll
        for (int e = 0; e < 2; e++) {
            const int k = k0 + e, ci = k >> 5, a = k & 31;
            const float* r0 = sW0 + (ci & 1) * 1024 + a * 32;
            const float* r1 = sW1 + (ci >> 1) * 1024 + n;
            float acc = 0.f;
            #pragma unroll 8
            for (int cc = 0; cc < 32; cc++) acc += r0[cc] * r1[cc * 32];
            v[e] = acc * W_SCALE;
        }
        float h0, l0, h1, l1;
        msplit(v[0], h0, l0);
        msplit(v[1], h1, l1);
        dst[i] = (term == 0) ? packh2(h0, h1) : packh2(l0, l1);
    }
}

__global__ void __launch_bounds__(TPB, 4)
mps_hmma_kernel(const float* __restrict__ x,
                const float* __restrict__ core0,
                const float* __restrict__ coreN,
                float* __restrict__ out, int B)
{
    __shared__ __align__(16) unsigned sW[2][4096];   // 2 stages x 16KB

    const int tid  = threadIdx.x;
    const int lane = tid & 31;
    const int w    = tid >> 5;
    const int q    = lane & 3;
    const int g    = lane >> 2;
    const int rowbase = blockIdx.x * ROWS_PER_CTA + w * 16;

    int rows[2];
    rows[0] = min(rowbase + g,     B - 1);
    rows[1] = min(rowbase + g + 8, B - 1);

    // prefetch pair-0 tile (16KB)
    {
        const unsigned* gsrc = g_Bt;
        const unsigned sb = smem_u32(&sW[0][0]);
        #pragma unroll
        for (int i = 0; i < 8; i++) {
            const int idx = tid + i * TPB;
            cp16(sb + idx * 16, gsrc + idx * 4);
        }
        cp_commit();
    }

    // ---- init acc = M0 (c-frag layout), then normalize to NORM_TGT ----
    float acc[16];
    #pragma unroll
    for (int rs = 0; rs < 2; rs++) {
        float s0, c0;
        __sincosf(HALF_PI * __ldg(x + (size_t)rows[rs] * L), &s0, &c0);
        #pragma unroll
        for (int j = 0; j < 4; j++)
            #pragma unroll
            for (int pp = 0; pp < 2; pp++) {
                const int col = 8 * j + 2 * q + pp;
                acc[4 * j + 2 * rs + pp] = c0 * core0[col] + s0 * core0[32 + col];
            }
    }
    #pragma unroll
    for (int rs = 0; rs < 2; rs++) {
        float ss = 0.f;
        #pragma unroll
        for (int j = 0; j < 4; j++) {
            const float v0 = acc[4 * j + 2 * rs];
            const float v1 = acc[4 * j + 2 * rs + 1];
            ss += v0 * v0 + v1 * v1;
        }
        ss += __shfl_xor_sync(0xffffffffu, ss, 1);
        ss += __shfl_xor_sync(0xffffffffu, ss, 2);
        const float r = NORM_TGT * rsqrtf(ss);
        #pragma unroll
        for (int j = 0; j < 4; j++) {
            acc[4 * j + 2 * rs]     *= r;
            acc[4 * j + 2 * rs + 1] *= r;
        }
    }

    // pair-0 scalars
    float sc[4][2];
    #pragma unroll
    for (int rs = 0; rs < 2; rs++) {
        float s1v, c1v, s2v, c2v;
        __sincosf(HALF_PI * __ldg(x + (size_t)rows[rs] * L + 1), &s1v, &c1v);
        __sincosf(HALF_PI * __ldg(x + (size_t)rows[rs] * L + 2), &s2v, &c2v);
        sc[0][rs] = c1v * c2v;  sc[1][rs] = s1v * c2v;
        sc[2][rs] = c1v * s2v;  sc[3][rs] = s1v * s2v;
    }

    // ---- 127 composite steps ----
    for (int p = 0; p < NPAIR; p++) {
        cp_wait0();
        __syncthreads();

        if (p + 1 < NPAIR) {
            const unsigned* gsrc = g_Bt + (size_t)(p + 1) * 4096;
            const unsigned sb = smem_u32(&sW[(p + 1) & 1][0]);
            #pragma unroll
            for (int i = 0; i < 8; i++) {
                const int idx = tid + i * TPB;
                cp16(sb + idx * 16, gsrc + idx * 4);
            }
            cp_commit();
        }

        const unsigned* W = &sW[p & 1][0];

        float na0[16], na1[16];                      // T-parity banks (8 MMA chains)
        #pragma unroll
        for (int k = 0; k < 16; k++) { na0[k] = 0.f; na1[k] = 0.f; }

        #pragma unroll
        for (int T = 0; T < 8; T++) {
            const int ci = T >> 1;
            const int j1 = 2 * (T & 1), j2 = j1 + 1;
            const float sc0 = sc[ci][0], sc1 = sc[ci][1];
            float* nacc = (T & 1) ? na1 : na0;

            const float v00 = sc0 * acc[4 * j1 + 0], v01 = sc0 * acc[4 * j1 + 1];
            const float v10 = sc1 * acc[4 * j1 + 2], v11 = sc1 * acc[4 * j1 + 3];
            const float v20 = sc0 * acc[4 * j2 + 0], v21 = sc0 * acc[4 * j2 + 1];
            const float v30 = sc1 * acc[4 * j2 + 2], v31 = sc1 * acc[4 * j2 + 3];

            float h00,l00,h01,l01,h10,l10,h11,l11,h20,l20,h21,l21,h30,l30,h31,l31;
            msplit(v00,h00,l00); msplit(v01,h01,l01);
            msplit(v10,h10,l10); msplit(v11,h11,l11);
            msplit(v20,h20,l20); msplit(v21,h21,l21);
            msplit(v30,h30,l30); msplit(v31,h31,l31);

            unsigned ahi[4], alo[4];
            ahi[0] = packh2(h00,h01); ahi[1] = packh2(h10,h11);
            ahi[2] = packh2(h20,h21); ahi[3] = packh2(h30,h31);
            alo[0] = packh2(l00,l01); alo[1] = packh2(l10,l11);
            alo[2] = packh2(l20,l21); alo[3] = packh2(l30,l31);

            #pragma unroll
            for (int j = 0; j < 4; j++) {
                const uint4 b = *reinterpret_cast<const uint4*>(
                    W + ((size_t)(T * 4 + j) * 32 + lane) * 4);
                mma16(&nacc[4 * j], ahi, b.x, b.y);   // hi*Bhi
                mma16(&nacc[4 * j], ahi, b.z, b.w);   // hi*Blo
                mma16(&nacc[4 * j], alo, b.x, b.y);   // lo*Bhi
            }
        }

        // next pair's scalars (x-only; overlaps in-flight MMAs)
        if (p + 1 < NPAIR) {
            #pragma unroll
            for (int rs = 0; rs < 2; rs++) {
                float s1v, c1v, s2v, c2v;
                __sincosf(HALF_PI * __ldg(x + (size_t)rows[rs] * L + (2 * p + 3)), &s1v, &c1v);
                __sincosf(HALF_PI * __ldg(x + (size_t)rows[rs] * L + (2 * p + 4)), &s2v, &c2v);
                sc[0][rs] = c1v * c2v;  sc[1][rs] = s1v * c2v;
                sc[2][rs] = c1v * s2v;  sc[3][rs] = s1v * s2v;
            }
        }

        // merge banks
        #pragma unroll
        for (int k = 0; k < 16; k++) acc[k] = na0[k] + na1[k];

        // rescale to NORM_TGT every 2 pairs (absorbs the x64 W scale; keeps
        // A-entries and their lo-parts in f16 normal range)
        if (p & 1) {
            #pragma unroll
            for (int rs = 0; rs < 2; rs++) {
                float ss = 0.f;
                #pragma unroll
                for (int j = 0; j < 4; j++) {
                    const float v0 = acc[4 * j + 2 * rs];
                    const float v1 = acc[4 * j + 2 * rs + 1];
                    ss += v0 * v0 + v1 * v1;
                }
                ss += __shfl_xor_sync(0xffffffffu, ss, 1);
                ss += __shfl_xor_sync(0xffffffffu, ss, 2);
                const float r = NORM_TGT * rsqrtf(ss);
                #pragma unroll
                for (int j = 0; j < 4; j++) {
                    acc[4 * j + 2 * rs]     *= r;
                    acc[4 * j + 2 * rs + 1] *= r;
                }
            }
        }
    }

    // ---- readout: eps-free unit normalize + coreN contraction ----
    #pragma unroll
    for (int rs = 0; rs < 2; rs++) {
        const int row = rowbase + g + 8 * rs;

        float ss = 0.f;
        #pragma unroll
        for (int j = 0; j < 4; j++) {
            const float v0 = acc[4 * j + 2 * rs];
            const float v1 = acc[4 * j + 2 * rs + 1];
            ss += v0 * v0 + v1 * v1;
        }
        ss += __shfl_xor_sync(0xffffffffu, ss, 1);
        ss += __shfl_xor_sync(0xffffffffu, ss, 2);
        const float inv = rsqrtf(ss);           // NO eps (R1 lesson)

        float sL, cL;
        __sincosf(HALF_PI * __ldg(x + (size_t)rows[rs] * L + (L - 1)), &sL, &cL);

        float lg[C];
        #pragma unroll
        for (int cc = 0; cc < C; cc++) lg[cc] = 0.f;
        #pragma unroll
        for (int j = 0; j < 4; j++)
            #pragma unroll
            for (int pp = 0; pp < 2; pp++) {
                const int col = 8 * j + 2 * q + pp;
                const float m = acc[4 * j + 2 * rs + pp];
                #pragma unroll
                for (int cc = 0; cc < C; cc++) {
                    const float wv = cL * coreN[col * C + cc]
                                   + sL * coreN[D * C + col * C + cc];
                    lg[cc] += m * wv;
                }
            }
        #pragma unroll
        for (int cc = 0; cc < C; cc++) {
            lg[cc] += __shfl_xor_sync(0xffffffffu, lg[cc], 1);
            lg[cc] += __shfl_xor_sync(0xffffffffu, lg[cc], 2);
        }
        if (q == 0 && row < B) {
            #pragma unroll
            for (int cc = 0; cc < C; cc++)
                out[(size_t)row * C + cc] = lg[cc] * inv;
        }
    }
}

extern "C" void kernel_launch(void* const* d_in, const int* in_sizes, int n_in,
                              void* d_out, int out_size)
{
    const float* x         = (const float*)d_in[0];
    const float* core0     = (const float*)d_in[1];
    const float* cores_mid = (const float*)d_in[2];
    const float* coreN     = (const float*)d_in[3];
    float* out = (float*)d_out;

    const int B = in_sizes[0] / L;
    const int grid = (B + ROWS_PER_CTA - 1) / ROWS_PER_CTA;   // 512 for B=32768

    prep_pairs<<<NPAIR, 256>>>(cores_mid);
    mps_hmma_kernel<<<grid, TPB>>>(x, core0, coreN, out, B);
}

// round 13
// speedup vs baseline: 1.7451x; 1.0585x over previous
#include <cuda_runtime.h>
#include <cuda_fp16.h>
#include <cstdint>

// CachedMPS on GB300 — fp16 m16n8k16 split HMMA chain, paired steps.
// R13: post-hoc pair-scalar application. Compute unscaled P[ci] = M x W[ci]
// (A split ONCE per pair from raw acc), then fold acc' = sum sc[ci]*P[ci].
// Removes the 4x-redundant per-ci A scale/split chain from the MMA critical
// path (MMAs now depend only on B LDS). Scale engineering from R12 kept:
// W x64 in prep, chain renormalized to 256 every 2 pairs, eps-free final
// unit-normalize. Split exact: hi = v & 0xFFFFE000, lo = v - hi.

#define DEV_INLINE __device__ __forceinline__

static constexpr int D     = 32;
static constexpr int L     = 256;
static constexpr int NPAIR = 127;
static constexpr int C     = 10;
static constexpr int TPB   = 128;             // 4 warps x 16 rows = 64 rows/CTA
static constexpr int ROWS_PER_CTA = 64;
static constexpr float HALF_PI = 1.57079632679489662f;
static constexpr float W_SCALE  = 64.0f;
static constexpr float NORM_TGT = 256.0f;
static constexpr unsigned H_MASK = 0xFFFFE000u;

// composite-W scratch: [NPAIR][4096] u32 (f16x2-packed hi/lo, frag-native)
__device__ unsigned g_Bt[(size_t)NPAIR * 4096];

DEV_INLINE unsigned smem_u32(const void* p) {
    unsigned r;
    asm("{ .reg .u64 t; cvta.to.shared.u64 t, %1; cvt.u32.u64 %0, t; }" : "=r"(r) : "l"(p));
    return r;
}
DEV_INLINE void cp16(unsigned dst, const void* src) {
    asm volatile("cp.async.cg.shared.global [%0], [%1], 16;" :: "r"(dst), "l"(src));
}
DEV_INLINE void cp_commit() { asm volatile("cp.async.commit_group;"); }
DEV_INLINE void cp_wait0()  { asm volatile("cp.async.wait_group 0;" ::: "memory"); }

DEV_INLINE unsigned packh2(float lo, float hi) {
    unsigned r; asm("cvt.rn.f16x2.f32 %0, %1, %2;" : "=r"(r) : "f"(hi), "f"(lo));
    return r;
}

DEV_INLINE void mma16(float* c, const unsigned* a, unsigned b0, unsigned b1) {
    asm("mma.sync.aligned.m16n8k16.row.col.f32.f16.f16.f32 "
        "{%0,%1,%2,%3}, {%4,%5,%6,%7}, {%8,%9}, {%0,%1,%2,%3};"
        : "+f"(c[0]), "+f"(c[1]), "+f"(c[2]), "+f"(c[3])
        : "r"(a[0]), "r"(a[1]), "r"(a[2]), "r"(a[3]), "r"(b0), "r"(b1));
}

DEV_INLINE void msplit(float v, float& hf, float& lf) {
    const unsigned h = __float_as_uint(v) & H_MASK;
    hf = __uint_as_float(h);
    lf = v - hf;
}

// ---- prep: composite pair products x64 -> f16 hi/lo, B-frag-native ----
// (layout verified R10/R12) u32 slot i: s=i&3 (0=hi r0,1=hi r1,2=lo r0,
// 3=lo r1), lane=(i>>2)&31, tj=i>>7: T=tj>>2, j=tj&3; k0=16T+2q+8r;
// k=ci*32+a; value = 64 * sum_cc W0[ci&1][a][cc]*W1[ci>>1][cc][n], n=8j+g.
__global__ void prep_pairs(const float* __restrict__ cores_mid) {
    __shared__ float sW0[2048], sW1[2048];
    const int p = blockIdx.x;
    const float* s0 = cores_mid + (size_t)(2 * p) * 2048;
    const float* s1 = cores_mid + (size_t)(2 * p + 1) * 2048;
    for (int i = threadIdx.x; i < 2048; i += blockDim.x) { sW0[i] = s0[i]; sW1[i] = s1[i]; }
    __syncthreads();

    unsigned* dst = g_Bt + (size_t)p * 4096;
    for (int i = threadIdx.x; i < 4096; i += blockDim.x) {
        const int s = i & 3, lane = (i >> 2) & 31, tj = i >> 7;
        const int T = tj >> 2, j = tj & 3;
        const int q = lane & 3, g = lane >> 2;
        const int reg = s & 1, term = s >> 1;
        const int k0 = 16 * T + 2 * q + 8 * reg;
        const int n  = 8 * j + g;

        float v[2];
        #pragma unroll
        for (int e = 0; e < 2; e++) {
            const int k = k0 + e, ci = k >> 5, a = k & 31;
            const float* r0 = sW0 + (ci & 1) * 1024 + a * 32;
            const float* r1 = sW1 + (ci >> 1) * 1024 + n;
            float acc = 0.f;
            #pragma unroll 8
            for (int cc = 0; cc < 32; cc++) acc += r0[cc] * r1[cc * 32];
            v[e] = acc * W_SCALE;
        }
        float h0, l0, h1, l1;
        msplit(v[0], h0, l0);
        msplit(v[1], h1, l1);
        dst[i] = (term == 0) ? packh2(h0, h1) : packh2(l0, l1);
    }
}

__global__ void __launch_bounds__(TPB, 4)
mps_hmma_kernel(const float* __restrict__ x,
                const float* __restrict__ core0,
                const float* __restrict__ coreN,
                float* __restrict__ out, int B)
{
    __shared__ __align__(16) unsigned sW[2][4096];   // 2 stages x 16KB

    const int tid  = threadIdx.x;
    const int lane = tid & 31;
    const int w    = tid >> 5;
    const int q    = lane & 3;
    const int g    = lane >> 2;
    const int rowbase = blockIdx.x * ROWS_PER_CTA + w * 16;

    int rows[2];
    rows[0] = min(rowbase + g,     B - 1);
    rows[1] = min(rowbase + g + 8, B - 1);

    // prefetch pair-0 tile (16KB)
    {
        const unsigned* gsrc = g_Bt;
        const unsigned sb = smem_u32(&sW[0][0]);
        #pragma unroll
        for (int i = 0; i < 8; i++) {
            const int idx = tid + i * TPB;
            cp16(sb + idx * 16, gsrc + idx * 4);
        }
        cp_commit();
    }

    // ---- init acc = M0 (c-frag layout), then normalize to NORM_TGT ----
    float acc[16];
    #pragma unroll
    for (int rs = 0; rs < 2; rs++) {
        float s0, c0;
        __sincosf(HALF_PI * __ldg(x + (size_t)rows[rs] * L), &s0, &c0);
        #pragma unroll
        for (int j = 0; j < 4; j++)
            #pragma unroll
            for (int pp = 0; pp < 2; pp++) {
                const int col = 8 * j + 2 * q + pp;
                acc[4 * j + 2 * rs + pp] = c0 * core0[col] + s0 * core0[32 + col];
            }
    }
    #pragma unroll
    for (int rs = 0; rs < 2; rs++) {
        float ss = 0.f;
        #pragma unroll
        for (int j = 0; j < 4; j++) {
            const float v0 = acc[4 * j + 2 * rs];
            const float v1 = acc[4 * j + 2 * rs + 1];
            ss += v0 * v0 + v1 * v1;
        }
        ss += __shfl_xor_sync(0xffffffffu, ss, 1);
        ss += __shfl_xor_sync(0xffffffffu, ss, 2);
        const float r = NORM_TGT * rsqrtf(ss);
        #pragma unroll
        for (int j = 0; j < 4; j++) {
            acc[4 * j + 2 * rs]     *= r;
            acc[4 * j + 2 * rs + 1] *= r;
        }
    }

    // pair-0 scalars
    float sc[4][2];
    #pragma unroll
    for (int rs = 0; rs < 2; rs++) {
        float s1v, c1v, s2v, c2v;
        __sincosf(HALF_PI * __ldg(x + (size_t)rows[rs] * L + 1), &s1v, &c1v);
        __sincosf(HALF_PI * __ldg(x + (size_t)rows[rs] * L + 2), &s2v, &c2v);
        sc[0][rs] = c1v * c2v;  sc[1][rs] = s1v * c2v;
        sc[2][rs] = c1v * s2v;  sc[3][rs] = s1v * s2v;
    }

    // ---- 127 composite steps ----
    for (int p = 0; p < NPAIR; p++) {
        cp_wait0();
        __syncthreads();

        if (p + 1 < NPAIR) {
            const unsigned* gsrc = g_Bt + (size_t)(p + 1) * 4096;
            const unsigned sb = smem_u32(&sW[(p + 1) & 1][0]);
            #pragma unroll
            for (int i = 0; i < 8; i++) {
                const int idx = tid + i * TPB;
                cp16(sb + idx * 16, gsrc + idx * 4);
            }
            cp_commit();
        }

        const unsigned* W = &sW[p & 1][0];

        // split A ONCE (unscaled): a-frag tk packs acc[8tk..8tk+7] pairwise
        unsigned ahi[2][4], alo[2][4];
        #pragma unroll
        for (int tk = 0; tk < 2; tk++)
            #pragma unroll
            for (int i = 0; i < 4; i++) {
                float h0, l0, h1, l1;
                msplit(acc[8 * tk + 2 * i],     h0, l0);
                msplit(acc[8 * tk + 2 * i + 1], h1, l1);
                ahi[tk][i] = packh2(h0, h1);
                alo[tk][i] = packh2(l0, l1);
            }

        float nacc[16];
        float P0[16], P1[16];   // ci-parity banks

        #pragma unroll
        for (int ci = 0; ci < 4; ci++) {
            float* P = (ci & 1) ? P1 : P0;
            #pragma unroll
            for (int k = 0; k < 16; k++) P[k] = 0.f;

            #pragma unroll
            for (int tk = 0; tk < 2; tk++) {
                const int T = 2 * ci + tk;
                #pragma unroll
                for (int j = 0; j < 4; j++) {
                    const uint4 b = *reinterpret_cast<const uint4*>(
                        W + ((size_t)(T * 4 + j) * 32 + lane) * 4);
                    mma16(&P[4 * j], ahi[tk], b.x, b.y);   // hi*Bhi
                    mma16(&P[4 * j], ahi[tk], b.z, b.w);   // hi*Blo
                    mma16(&P[4 * j], alo[tk], b.x, b.y);   // lo*Bhi
                }
            }

            // fold this family: nacc (+)= sc[ci][rs] * P
            const float s0 = sc[ci][0], s1 = sc[ci][1];
            if (ci == 0) {
                #pragma unroll
                for (int j = 0; j < 4; j++) {
                    nacc[4 * j + 0] = s0 * P[4 * j + 0];
                    nacc[4 * j + 1] = s0 * P[4 * j + 1];
                    nacc[4 * j + 2] = s1 * P[4 * j + 2];
                    nacc[4 * j + 3] = s1 * P[4 * j + 3];
                }
            } else {
                #pragma unroll
                for (int j = 0; j < 4; j++) {
                    nacc[4 * j + 0] = fmaf(s0, P[4 * j + 0], nacc[4 * j + 0]);
                    nacc[4 * j + 1] = fmaf(s0, P[4 * j + 1], nacc[4 * j + 1]);
                    nacc[4 * j + 2] = fmaf(s1, P[4 * j + 2], nacc[4 * j + 2]);
                    nacc[4 * j + 3] = fmaf(s1, P[4 * j + 3], nacc[4 * j + 3]);
                }
            }
        }

        // next pair's scalars (x-only; overlaps in-flight MMAs)
        if (p + 1 < NPAIR) {
            #pragma unroll
            for (int rs = 0; rs < 2; rs++) {
                float s1v, c1v, s2v, c2v;
                __sincosf(HALF_PI * __ldg(x + (size_t)rows[rs] * L + (2 * p + 3)), &s1v, &c1v);
                __sincosf(HALF_PI * __ldg(x + (size_t)rows[rs] * L + (2 * p + 4)), &s2v, &c2v);
                sc[0][rs] = c1v * c2v;  sc[1][rs] = s1v * c2v;
                sc[2][rs] = c1v * s2v;  sc[3][rs] = s1v * s2v;
            }
        }

        #pragma unroll
        for (int k = 0; k < 16; k++) acc[k] = nacc[k];

        // rescale to NORM_TGT every 2 pairs (absorbs x64 W scale; keeps
        // acc entries + lo-parts in f16 range for the next A-split)
        if (p & 1) {
            #pragma unroll
            for (int rs = 0; rs < 2; rs++) {
                float ss = 0.f;
                #pragma unroll
                for (int j = 0; j < 4; j++) {
                    const float v0 = acc[4 * j + 2 * rs];
                    const float v1 = acc[4 * j + 2 * rs + 1];
                    ss += v0 * v0 + v1 * v1;
                }
                ss += __shfl_xor_sync(0xffffffffu, ss, 1);
                ss += __shfl_xor_sync(0xffffffffu, ss, 2);
                const float r = NORM_TGT * rsqrtf(ss);
                #pragma unroll
                for (int j = 0; j < 4; j++) {
                    acc[4 * j + 2 * rs]     *= r;
                    acc[4 * j + 2 * rs + 1] *= r;
                }
            }
        }
    }

    // ---- readout: eps-free unit normalize + coreN contraction ----
    #pragma unroll
    for (int rs = 0; rs < 2; rs++) {
        const int row = rowbase + g + 8 * rs;

        float ss = 0.f;
        #pragma unroll
        for (int j = 0; j < 4; j++) {
            const float v0 = acc[4 * j + 2 * rs];
            const float v1 = acc[4 * j + 2 * rs + 1];
            ss += v0 * v0 + v1 * v1;
        }
        ss += __shfl_xor_sync(0xffffffffu, ss, 1);
        ss += __shfl_xor_sync(0xffffffffu, ss, 2);
        const float inv = rsqrtf(ss);           // NO eps (R1 lesson)

        float sL, cL;
        __sincosf(HALF_PI * __ldg(x + (size_t)rows[rs] * L + (L - 1)), &sL, &cL);

        float lg[C];
        #pragma unroll
        for (int cc = 0; cc < C; cc++) lg[cc] = 0.f;
        #pragma unroll
        for (int j = 0; j < 4; j++)
            #pragma unroll
            for (int pp = 0; pp < 2; pp++) {
                const int col = 8 * j + 2 * q + pp;
                const float m = acc[4 * j + 2 * rs + pp];
                #pragma unroll
                for (int cc = 0; cc < C; cc++) {
                    const float wv = cL * coreN[col * C + cc]
                                   + sL * coreN[D * C + col * C + cc];
                    lg[cc] += m * wv;
                }
            }
        #pragma unroll
        for (int cc = 0; cc < C; cc++) {
            lg[cc] += __shfl_xor_sync(0xffffffffu, lg[cc], 1);
            lg[cc] += __shfl_xor_sync(0xffffffffu, lg[cc], 2);
        }
        if (q == 0 && row < B) {
            #pragma unroll
            for (int cc = 0; cc < C; cc++)
                out[(size_t)row * C + cc] = lg[cc] * inv;
        }
    }
}

extern "C" void kernel_launch(void* const* d_in, const int* in_sizes, int n_in,
                              void* d_out, int out_size)
{
    const float* x         = (const float*)d_in[0];
    const float* core0     = (const float*)d_in[1];
    const float* cores_mid = (const float*)d_in[2];
    const float* coreN     = (const float*)d_in[3];
    float* out = (float*)d_out;

    const int B = in_sizes[0] / L;
    const int grid = (B + ROWS_PER_CTA - 1) / ROWS_PER_CTA;   // 512 for B=32768

    prep_pairs<<<NPAIR, 256>>>(cores_mid);
    mps_hmma_kernel<<<grid, TPB>>>(x, core0, coreN, out, B);
}